// round 5
// baseline (speedup 1.0000x reference)
#include <cuda_runtime.h>

typedef unsigned long long u64;

#define NG   256
#define NN   64
#define KNN  24
#define HID  128
#define XSTR 132   // float stride for Xs (padded, bank-spread for dist phase)
#define PSTR 128   // float stride for As/Ps (128B-aligned rows for gather)
#define DPAD 68    // uint stride for 64x64 key matrix
#define NT   256   // threads per CTA

// k-pair-packed weights: each u64 = (w[2kp][c], w[2kp+1][c]) as two fp32 lanes
__device__ u64 g_Wcp[64 * 256];   // edge-conv: cols 0..127 = Wt-Wb ('a'), 128..255 = Wb ('p')
__device__ u64 g_W2p[64 * 128];
__device__ u64 g_W1p[8 * 128];    // K=15 zero-padded to 16

__device__ __forceinline__ void fma2(u64& d, u64 a, u64 b) {
    asm("fma.rn.f32x2 %0, %1, %2, %0;" : "+l"(d) : "l"(a), "l"(b));
}
__device__ __forceinline__ float2 upk(u64 v) {
    float2 f; asm("mov.b64 {%0, %1}, %2;" : "=f"(f.x), "=f"(f.y) : "l"(v)); return f;
}
__device__ __forceinline__ u64 pk(float lo, float hi) {
    u64 r; asm("mov.b64 %0, {%1, %2};" : "=l"(r) : "f"(lo), "f"(hi)); return r;
}
__device__ __forceinline__ float hadd(u64 v) {
    float2 f = upk(v); return f.x + f.y;
}
__device__ __forceinline__ float elu1(float x) {
    return x > 0.f ? x : (__expf(x) - 1.f);
}
// monotonic uint encoding of float (total order matching < on floats)
__device__ __forceinline__ unsigned fkey(float d) {
    unsigned u = __float_as_uint(d);
    return ((int)u < 0) ? ~u : (u | 0x80000000u);
}

__global__ void prep_kernel(const float* __restrict__ Wc,
                            const float* __restrict__ W1,
                            const float* __restrict__ W2) {
    int i = blockIdx.x * blockDim.x + threadIdx.x;
    if (i < 64 * 256) {
        int kp = i >> 8, c = i & 255;
        float lo, hi;
        if (c < HID) {
            lo = Wc[(2 * kp) * HID + c]     - Wc[(HID + 2 * kp) * HID + c];
            hi = Wc[(2 * kp + 1) * HID + c] - Wc[(HID + 2 * kp + 1) * HID + c];
        } else {
            lo = Wc[(HID + 2 * kp) * HID + (c - HID)];
            hi = Wc[(HID + 2 * kp + 1) * HID + (c - HID)];
        }
        g_Wcp[i] = pk(lo, hi);
    }
    int j = i - 64 * 256;
    if (j >= 0 && j < 64 * 128) {
        int kp = j >> 7, c = j & 127;
        g_W2p[j] = pk(W2[(2 * kp) * HID + c], W2[(2 * kp + 1) * HID + c]);
    }
    int l = i - 64 * 256 - 64 * 128;
    if (l >= 0 && l < 8 * 128) {
        int kp = l >> 7, c = l & 127;
        float lo = W1[(2 * kp) * HID + c];
        float hi = (2 * kp + 1 < 15) ? W1[(2 * kp + 1) * HID + c] : 0.f;
        g_W1p[l] = pk(lo, hi);
    }
}

// Out[64x128] = elu( Xin[64 x 2*KP] @ W + bias ). 256 threads, 8 rows x 4 cols per thread.
__device__ __forceinline__ void gemm_act(const float* __restrict__ Xin, int xs, int KP,
                                         const u64* __restrict__ Wp,
                                         const float* __restrict__ bias,
                                         float* __restrict__ Out, int os, int t) {
    int n0 = (t >> 5) * 8;
    int c0 = (t & 31) * 4;
    u64 acc[8][4];
#pragma unroll
    for (int i = 0; i < 8; i++) { acc[i][0] = 0; acc[i][1] = 0; acc[i][2] = 0; acc[i][3] = 0; }
#pragma unroll 4
    for (int kp = 0; kp < KP; kp++) {
        const u64* wr = Wp + kp * 128 + c0;
        ulonglong2 wa = *(const ulonglong2*)(wr);
        ulonglong2 wb = *(const ulonglong2*)(wr + 2);
        u64 xv[8];
#pragma unroll
        for (int i = 0; i < 8; i++) xv[i] = *(const u64*)(Xin + (n0 + i) * xs + 2 * kp);
#pragma unroll
        for (int i = 0; i < 8; i++) {
            fma2(acc[i][0], xv[i], wa.x);
            fma2(acc[i][1], xv[i], wa.y);
            fma2(acc[i][2], xv[i], wb.x);
            fma2(acc[i][3], xv[i], wb.y);
        }
    }
    float4 b = *(const float4*)(bias + c0);
#pragma unroll
    for (int i = 0; i < 8; i++) {
        float4 r;
        r.x = elu1(hadd(acc[i][0]) + b.x);
        r.y = elu1(hadd(acc[i][1]) + b.y);
        r.z = elu1(hadd(acc[i][2]) + b.z);
        r.w = elu1(hadd(acc[i][3]) + b.w);
        *(float4*)(Out + (n0 + i) * os + c0) = r;
    }
}

// Fused edge gemm: A[64x128] = X @ Wcat[:,0:128], P[64x128] = X @ Wcat[:,128:256].
// One X stream serves both outputs. 8 rows x (4+4) cols per thread.
__device__ __forceinline__ void gemm_edge(const float* __restrict__ Xin,
                                          float* __restrict__ Aout,
                                          float* __restrict__ Pout, int t) {
    int n0 = (t >> 5) * 8;
    int c0 = (t & 31) * 4;
    u64 aA[8][4], aP[8][4];
#pragma unroll
    for (int i = 0; i < 8; i++)
#pragma unroll
        for (int j = 0; j < 4; j++) { aA[i][j] = 0; aP[i][j] = 0; }
#pragma unroll 2
    for (int kp = 0; kp < 64; kp++) {
        const u64* wr = g_Wcp + kp * 256 + c0;
        ulonglong2 wa0 = *(const ulonglong2*)(wr);
        ulonglong2 wa1 = *(const ulonglong2*)(wr + 2);
        ulonglong2 wp0 = *(const ulonglong2*)(wr + 128);
        ulonglong2 wp1 = *(const ulonglong2*)(wr + 130);
        u64 xv[8];
#pragma unroll
        for (int i = 0; i < 8; i++) xv[i] = *(const u64*)(Xin + (n0 + i) * XSTR + 2 * kp);
#pragma unroll
        for (int i = 0; i < 8; i++) {
            fma2(aA[i][0], xv[i], wa0.x);
            fma2(aA[i][1], xv[i], wa0.y);
            fma2(aA[i][2], xv[i], wa1.x);
            fma2(aA[i][3], xv[i], wa1.y);
            fma2(aP[i][0], xv[i], wp0.x);
            fma2(aP[i][1], xv[i], wp0.y);
            fma2(aP[i][2], xv[i], wp1.x);
            fma2(aP[i][3], xv[i], wp1.y);
        }
    }
#pragma unroll
    for (int i = 0; i < 8; i++) {
        *(float4*)(Aout + (n0 + i) * PSTR + c0) =
            make_float4(hadd(aA[i][0]), hadd(aA[i][1]), hadd(aA[i][2]), hadd(aA[i][3]));
        *(float4*)(Pout + (n0 + i) * PSTR + c0) =
            make_float4(hadd(aP[i][0]), hadd(aP[i][1]), hadd(aP[i][2]), hadd(aP[i][3]));
    }
}

// shared-memory layout (floats)
#define OFF_XS   0
#define OFF_AS   (NN * XSTR)                  // 8448  (byte 33792, 128B aligned)
#define OFF_PS   (OFF_AS + NN * PSTR)         // 16640 (byte 66560, 128B aligned)
#define OFF_IDX  (OFF_PS + NN * PSTR)         // 24832
#define OFF_SQ   (OFF_IDX + NN * KNN)         // 26368
#define OFF_HD   (OFF_SQ + NN)                // 26432
#define SMEM_FLOATS (OFF_HD + 256)            // 26688

__global__ __launch_bounds__(NT, 2)
void net_kernel(const float* __restrict__ x_pf,
                const float* __restrict__ b1, const float* __restrict__ b2,
                const float* __restrict__ bc,
                const float* __restrict__ Wo1, const float* __restrict__ bo1,
                const float* __restrict__ Wo2, const float* __restrict__ bo2,
                const float* __restrict__ Wo3, const float* __restrict__ bo3,
                const float* __restrict__ Wo4, const float* __restrict__ bo4,
                float* __restrict__ out, int write_batch) {
    extern __shared__ __align__(128) float sm[];
    float* Xs = sm + OFF_XS;          // 64 x XSTR
    float* As = sm + OFF_AS;          // 64 x PSTR ('a' term; aliases keys + Xi scratch)
    float* Ps = sm + OFF_PS;          // 64 x PSTR ('p' term; h1 scratch in stage 1)
    int*   idxs = (int*)(sm + OFF_IDX);
    float* sq = sm + OFF_SQ;
    float* hd = sm + OFF_HD;
    unsigned* dsu = (unsigned*)As;    // 64 x DPAD 32-bit keys

    int g = blockIdx.x;
    int t = threadIdx.x;

    // ---------------- Stage 1: h = elu(elu(x@W1+b1)@W2+b2) ----------------
    float* Xi = As;  // temp [64][16], col 15 zeroed (k padding for packed W1)
    for (int i = t; i < NN * 16; i += NT) {
        int n = i >> 4, f = i & 15;
        Xi[i] = (f < 15) ? x_pf[(g * NN + n) * 15 + f] : 0.f;
    }
    __syncthreads();
    gemm_act(Xi, 16, 8, g_W1p, b1, Ps, PSTR, t);
    __syncthreads();
    gemm_act(Ps, PSTR, 64, g_W2p, b2, Xs, XSTR, t);

    // ---------------- 3 x EdgeConv ----------------
    for (int layer = 0; layer < 3; layer++) {
        __syncthreads();  // Xs ready
        // squared norms (packed over k)
        if (t < NN) {
            u64 a0 = 0, a1 = 0;
#pragma unroll 8
            for (int k4 = 0; k4 < 32; k4++) {
                ulonglong2 v = *(const ulonglong2*)(Xs + t * XSTR + k4 * 4);
                fma2(a0, v.x, v.x);
                fma2(a1, v.y, v.y);
            }
            sq[t] = hadd(a0) + hadd(a1);
        }
        __syncthreads();
        // pairwise distance keys: 4 rows x 4 strided cols per thread
        {
            int r0 = (t >> 4) * 4;       // 16 groups x 4 rows
            int cbase = t & 15;          // cols cbase + 16*j
            u64 acc2[4][4];
#pragma unroll
            for (int i = 0; i < 4; i++)
#pragma unroll
                for (int j = 0; j < 4; j++) acc2[i][j] = 0;
#pragma unroll 2
            for (int k4 = 0; k4 < 32; k4++) {
                ulonglong2 av[4], bv[4];
#pragma unroll
                for (int i = 0; i < 4; i++) av[i] = *(const ulonglong2*)(Xs + (r0 + i) * XSTR + k4 * 4);
#pragma unroll
                for (int j = 0; j < 4; j++) bv[j] = *(const ulonglong2*)(Xs + (cbase + 16 * j) * XSTR + k4 * 4);
#pragma unroll
                for (int i = 0; i < 4; i++)
#pragma unroll
                    for (int j = 0; j < 4; j++) {
                        fma2(acc2[i][j], av[i].x, bv[j].x);
                        fma2(acc2[i][j], av[i].y, bv[j].y);
                    }
            }
#pragma unroll
            for (int i = 0; i < 4; i++)
#pragma unroll
                for (int j = 0; j < 4; j++) {
                    int cc = cbase + 16 * j;
                    float d = sq[r0 + i] + sq[cc] - 2.f * hadd(acc2[i][j]);
                    dsu[(r0 + i) * DPAD + cc] = fkey(d);
                }
        }
        __syncthreads();
        // exact top-K by rank counting (keys assumed distinct; rank is the slot)
        {
            int i = t >> 2, jb = (t & 3) * 16;
            unsigned kj[16];
#pragma unroll
            for (int jj = 0; jj < 16; jj++) kj[jj] = dsu[i * DPAD + jb + jj];
            int rk[16];
#pragma unroll
            for (int jj = 0; jj < 16; jj++) rk[jj] = 0;
#pragma unroll 4
            for (int m = 0; m < 64; m++) {
                unsigned km = dsu[i * DPAD + m];
#pragma unroll
                for (int jj = 0; jj < 16; jj++) rk[jj] += (km < kj[jj]) ? 1 : 0;
            }
#pragma unroll
            for (int jj = 0; jj < 16; jj++)
                if (rk[jj] < KNN) idxs[i * KNN + rk[jj]] = jb + jj;
        }
        __syncthreads();  // keys dead; GEMM may overwrite As
        gemm_edge(Xs, As, Ps, t);
        __syncthreads();
        // gather-max over neighbors (elu is monotonic: max then one elu)
        // 8 lanes span 128B of each row -> aligned full-line wavefronts
        {
            int cb = t & 7;
#pragma unroll
            for (int half = 0; half < 2; half++) {
                int n = (t >> 3) + 32 * half;
                int id[KNN];
#pragma unroll
                for (int k = 0; k < KNN; k++) id[k] = idxs[n * KNN + k];
#pragma unroll
                for (int c4 = cb; c4 < 32; c4 += 8) {
                    float4 mx = make_float4(-3.4e38f, -3.4e38f, -3.4e38f, -3.4e38f);
#pragma unroll
                    for (int k = 0; k < KNN; k++) {
                        const float4 v = *(const float4*)(Ps + id[k] * PSTR + c4 * 4);
                        mx.x = fmaxf(mx.x, v.x); mx.y = fmaxf(mx.y, v.y);
                        mx.z = fmaxf(mx.z, v.z); mx.w = fmaxf(mx.w, v.w);
                    }
                    float4 a = *(const float4*)(As + n * PSTR + c4 * 4);
                    float4 bcv = *(const float4*)(bc + c4 * 4);
                    float4 r;
                    r.x = elu1(mx.x + a.x + bcv.x);
                    r.y = elu1(mx.y + a.y + bcv.y);
                    r.z = elu1(mx.z + a.z + bcv.z);
                    r.w = elu1(mx.w + a.w + bcv.w);
                    *(float4*)(Xs + n * XSTR + c4 * 4) = r;
                }
            }
        }
    }
    __syncthreads();

    // ---------------- pool + head MLP ----------------
    float* pooled = hd;        // 128
    float* o1 = hd + 128;      // 64
    float* o2 = hd + 192;      // 32
    float* o3 = hd + 224;      // 32
    if (t < 128) {
        float s = 0.f;
#pragma unroll 8
        for (int n = 0; n < NN; n++) s += Xs[n * XSTR + t];
        pooled[t] = s;
    }
    __syncthreads();
    if (t < 64) {
        float s = bo1[t];
        for (int k = 0; k < 128; k++) s = fmaf(pooled[k], Wo1[k * 64 + t], s);
        o1[t] = elu1(s);
    }
    __syncthreads();
    if (t < 32) {
        float s = bo2[t];
        for (int k = 0; k < 64; k++) s = fmaf(o1[k], Wo2[k * 32 + t], s);
        o2[t] = elu1(s);
    }
    __syncthreads();
    if (t < 32) {
        float s = bo3[t];
        for (int k = 0; k < 32; k++) s = fmaf(o2[k], Wo3[k * 32 + t], s);
        o3[t] = elu1(s);
    }
    __syncthreads();
    if (t < 8) {
        float s = bo4[t];
        for (int k = 0; k < 32; k++) s = fmaf(o3[k], Wo4[k * 8 + t], s);
        out[g * 8 + t] = s;
    }
    if (write_batch) {
        for (int l = t; l < NN; l += NT)
            out[NG * 8 + g * NN + l] = (float)g;
    }
}

static const int SMEM_BYTES = SMEM_FLOATS * 4;  // 106752

extern "C" void kernel_launch(void* const* d_in, const int* in_sizes, int n_in,
                              void* d_out, int out_size) {
    const float* x_pf = (const float*)d_in[0];
    // d_in[1] = batch_pf (implicit: node n belongs to graph n/64)
    const float* W1  = (const float*)d_in[2];
    const float* b1  = (const float*)d_in[3];
    const float* W2  = (const float*)d_in[4];
    const float* b2  = (const float*)d_in[5];
    const float* Wc  = (const float*)d_in[6];
    const float* bc  = (const float*)d_in[7];
    const float* Wo1 = (const float*)d_in[8];
    const float* bo1 = (const float*)d_in[9];
    const float* Wo2 = (const float*)d_in[10];
    const float* bo2 = (const float*)d_in[11];
    const float* Wo3 = (const float*)d_in[12];
    const float* bo3 = (const float*)d_in[13];
    const float* Wo4 = (const float*)d_in[14];
    const float* bo4 = (const float*)d_in[15];

    cudaFuncSetAttribute(net_kernel, cudaFuncAttributeMaxDynamicSharedMemorySize, SMEM_BYTES);

    prep_kernel<<<100, 256>>>(Wc, W1, W2);

    int write_batch = (out_size >= NG * 8 + NG * NN) ? 1 : 0;
    net_kernel<<<NG, NT, SMEM_BYTES>>>(x_pf, b1, b2, bc,
                                       Wo1, bo1, Wo2, bo2, Wo3, bo3, Wo4, bo4,
                                       (float*)d_out, write_batch);
}

// round 6
// speedup vs baseline: 2.8728x; 2.8728x over previous
#include <cuda_runtime.h>

typedef unsigned long long u64;

#define NG   256
#define NN   64
#define KNN  24
#define HID  128
#define NPAD 132   // float stride for all 64x128 tiles (rows spread over banks: base = 4*row mod 32)
#define DPAD 68    // uint stride for 64x64 key matrix
#define NT   256   // threads per CTA

// k-pair-packed weights: each u64 = (w[2kp][c], w[2kp+1][c]) as two fp32 lanes
__device__ u64 g_Wcp[64 * 256];   // edge-conv: cols 0..127 = Wt-Wb ('a'), 128..255 = Wb ('p')
__device__ u64 g_W2p[64 * 128];
__device__ u64 g_W1p[8 * 128];    // K=15 zero-padded to 16

__device__ __forceinline__ void fma2(u64& d, u64 a, u64 b) {
    asm("fma.rn.f32x2 %0, %1, %2, %0;" : "+l"(d) : "l"(a), "l"(b));
}
__device__ __forceinline__ float2 upk(u64 v) {
    float2 f; asm("mov.b64 {%0, %1}, %2;" : "=f"(f.x), "=f"(f.y) : "l"(v)); return f;
}
__device__ __forceinline__ u64 pk(float lo, float hi) {
    u64 r; asm("mov.b64 %0, {%1, %2};" : "=l"(r) : "f"(lo), "f"(hi)); return r;
}
__device__ __forceinline__ float hadd(u64 v) {
    float2 f = upk(v); return f.x + f.y;
}
__device__ __forceinline__ float elu1(float x) {
    return x > 0.f ? x : (__expf(x) - 1.f);
}
// monotonic uint encoding of float (total order matching < on floats)
__device__ __forceinline__ unsigned fkey(float d) {
    unsigned u = __float_as_uint(d);
    return ((int)u < 0) ? ~u : (u | 0x80000000u);
}

__global__ void prep_kernel(const float* __restrict__ Wc,
                            const float* __restrict__ W1,
                            const float* __restrict__ W2) {
    int i = blockIdx.x * blockDim.x + threadIdx.x;
    if (i < 64 * 256) {
        int kp = i >> 8, c = i & 255;
        float lo, hi;
        if (c < HID) {
            lo = Wc[(2 * kp) * HID + c]     - Wc[(HID + 2 * kp) * HID + c];
            hi = Wc[(2 * kp + 1) * HID + c] - Wc[(HID + 2 * kp + 1) * HID + c];
        } else {
            lo = Wc[(HID + 2 * kp) * HID + (c - HID)];
            hi = Wc[(HID + 2 * kp + 1) * HID + (c - HID)];
        }
        g_Wcp[i] = pk(lo, hi);
    }
    int j = i - 64 * 256;
    if (j >= 0 && j < 64 * 128) {
        int kp = j >> 7, c = j & 127;
        g_W2p[j] = pk(W2[(2 * kp) * HID + c], W2[(2 * kp + 1) * HID + c]);
    }
    int l = i - 64 * 256 - 64 * 128;
    if (l >= 0 && l < 8 * 128) {
        int kp = l >> 7, c = l & 127;
        float lo = W1[(2 * kp) * HID + c];
        float hi = (2 * kp + 1 < 15) ? W1[(2 * kp + 1) * HID + c] : 0.f;
        g_W1p[l] = pk(lo, hi);
    }
}

// Out[64x128] = elu( Xin[64 x 2*KP] @ W + bias ). 256 threads, 8 rows x 4 cols per thread.
__device__ __forceinline__ void gemm_act(const float* __restrict__ Xin, int xs, int KP,
                                         const u64* __restrict__ Wp,
                                         const float* __restrict__ bias,
                                         float* __restrict__ Out, int t) {
    int n0 = (t >> 5) * 8;
    int c0 = (t & 31) * 4;
    u64 acc[8][4];
#pragma unroll
    for (int i = 0; i < 8; i++) { acc[i][0] = 0; acc[i][1] = 0; acc[i][2] = 0; acc[i][3] = 0; }
#pragma unroll 4
    for (int kp = 0; kp < KP; kp++) {
        const u64* wr = Wp + kp * 128 + c0;
        ulonglong2 wa = *(const ulonglong2*)(wr);
        ulonglong2 wb = *(const ulonglong2*)(wr + 2);
        u64 xv[8];
#pragma unroll
        for (int i = 0; i < 8; i++) xv[i] = *(const u64*)(Xin + (n0 + i) * xs + 2 * kp);
#pragma unroll
        for (int i = 0; i < 8; i++) {
            fma2(acc[i][0], xv[i], wa.x);
            fma2(acc[i][1], xv[i], wa.y);
            fma2(acc[i][2], xv[i], wb.x);
            fma2(acc[i][3], xv[i], wb.y);
        }
    }
    float4 b = *(const float4*)(bias + c0);
#pragma unroll
    for (int i = 0; i < 8; i++) {
        float4 r;
        r.x = elu1(hadd(acc[i][0]) + b.x);
        r.y = elu1(hadd(acc[i][1]) + b.y);
        r.z = elu1(hadd(acc[i][2]) + b.z);
        r.w = elu1(hadd(acc[i][3]) + b.w);
        *(float4*)(Out + (n0 + i) * NPAD + c0) = r;
    }
}

// Out[64x128] = Xin[64x128] @ W (no bias/act). W k-pair packed, row stride 256.
__device__ __forceinline__ void gemm_raw(const float* __restrict__ Xin,
                                         const u64* __restrict__ Wp,
                                         float* __restrict__ Out, int t) {
    int n0 = (t >> 5) * 8;
    int c0 = (t & 31) * 4;
    u64 acc[8][4];
#pragma unroll
    for (int i = 0; i < 8; i++) { acc[i][0] = 0; acc[i][1] = 0; acc[i][2] = 0; acc[i][3] = 0; }
#pragma unroll 4
    for (int kp = 0; kp < 64; kp++) {
        const u64* wr = Wp + kp * 256 + c0;
        ulonglong2 wa = *(const ulonglong2*)(wr);
        ulonglong2 wb = *(const ulonglong2*)(wr + 2);
        u64 xv[8];
#pragma unroll
        for (int i = 0; i < 8; i++) xv[i] = *(const u64*)(Xin + (n0 + i) * NPAD + 2 * kp);
#pragma unroll
        for (int i = 0; i < 8; i++) {
            fma2(acc[i][0], xv[i], wa.x);
            fma2(acc[i][1], xv[i], wa.y);
            fma2(acc[i][2], xv[i], wb.x);
            fma2(acc[i][3], xv[i], wb.y);
        }
    }
#pragma unroll
    for (int i = 0; i < 8; i++) {
        *(float4*)(Out + (n0 + i) * NPAD + c0) =
            make_float4(hadd(acc[i][0]), hadd(acc[i][1]), hadd(acc[i][2]), hadd(acc[i][3]));
    }
}

__global__ __launch_bounds__(NT, 2)
void net_kernel(const float* __restrict__ x_pf,
                const float* __restrict__ b1, const float* __restrict__ b2,
                const float* __restrict__ bc,
                const float* __restrict__ Wo1, const float* __restrict__ bo1,
                const float* __restrict__ Wo2, const float* __restrict__ bo2,
                const float* __restrict__ Wo3, const float* __restrict__ bo3,
                const float* __restrict__ Wo4, const float* __restrict__ bo4,
                float* __restrict__ out, int write_batch) {
    extern __shared__ __align__(16) float sm[];
    float* Xs = sm;                   // 64 x NPAD current node features
    float* As = Xs + NN * NPAD;       // 64 x NPAD 'a' term (aliases keys + Xi scratch)
    float* Ps = As + NN * NPAD;       // 64 x NPAD 'p' term (h1 scratch in stage 1)
    int*   idxs = (int*)(Ps + NN * NPAD);          // 64*24 KNN indices
    float* sq = (float*)(idxs + NN * KNN);         // 64 squared norms
    float* hd = sq + NN;                           // 256 floats head scratch
    unsigned* dsu = (unsigned*)As;                 // 64 x DPAD 32-bit keys

    int g = blockIdx.x;
    int t = threadIdx.x;

    // ---------------- Stage 1: h = elu(elu(x@W1+b1)@W2+b2) ----------------
    float* Xi = As;  // temp [64][16], col 15 zeroed (k padding for packed W1)
    for (int i = t; i < NN * 16; i += NT) {
        int n = i >> 4, f = i & 15;
        Xi[i] = (f < 15) ? x_pf[(g * NN + n) * 15 + f] : 0.f;
    }
    __syncthreads();
    gemm_act(Xi, 16, 8, g_W1p, b1, Ps, t);
    __syncthreads();
    gemm_act(Ps, NPAD, 64, g_W2p, b2, Xs, t);

    // ---------------- 3 x EdgeConv ----------------
    for (int layer = 0; layer < 3; layer++) {
        __syncthreads();  // Xs ready
        // squared norms (packed over k)
        if (t < NN) {
            u64 a0 = 0, a1 = 0;
#pragma unroll 8
            for (int k4 = 0; k4 < 32; k4++) {
                ulonglong2 v = *(const ulonglong2*)(Xs + t * NPAD + k4 * 4);
                fma2(a0, v.x, v.x);
                fma2(a1, v.y, v.y);
            }
            sq[t] = hadd(a0) + hadd(a1);
        }
        __syncthreads();
        // pairwise distance keys: 4 rows x 4 strided cols per thread.
        // bv rows {c, c+16, c+32, c+48}: lane bases spread (bank 4*c) -> 2-way worst case.
        {
            int r0 = (t >> 4) * 4;       // 16 groups x 4 consecutive rows
            int cbase = t & 15;          // cols cbase + 16*j
            u64 acc2[4][4];
#pragma unroll
            for (int i = 0; i < 4; i++)
#pragma unroll
                for (int j = 0; j < 4; j++) acc2[i][j] = 0;
#pragma unroll 2
            for (int k4 = 0; k4 < 32; k4++) {
                ulonglong2 av[4], bv[4];
#pragma unroll
                for (int i = 0; i < 4; i++) av[i] = *(const ulonglong2*)(Xs + (r0 + i) * NPAD + k4 * 4);
#pragma unroll
                for (int j = 0; j < 4; j++) bv[j] = *(const ulonglong2*)(Xs + (cbase + 16 * j) * NPAD + k4 * 4);
#pragma unroll
                for (int i = 0; i < 4; i++)
#pragma unroll
                    for (int j = 0; j < 4; j++) {
                        fma2(acc2[i][j], av[i].x, bv[j].x);
                        fma2(acc2[i][j], av[i].y, bv[j].y);
                    }
            }
#pragma unroll
            for (int i = 0; i < 4; i++)
#pragma unroll
                for (int j = 0; j < 4; j++) {
                    int cc = cbase + 16 * j;
                    float d = sq[r0 + i] + sq[cc] - 2.f * hadd(acc2[i][j]);
                    dsu[(r0 + i) * DPAD + cc] = fkey(d);
                }
        }
        __syncthreads();
        // exact top-K by rank counting (keys assumed distinct; rank is the slot)
        {
            int i = t >> 2, jb = (t & 3) * 16;
            unsigned kj[16];
#pragma unroll
            for (int jj = 0; jj < 16; jj++) kj[jj] = dsu[i * DPAD + jb + jj];
            int rk[16];
#pragma unroll
            for (int jj = 0; jj < 16; jj++) rk[jj] = 0;
#pragma unroll 4
            for (int m = 0; m < 64; m++) {
                unsigned km = dsu[i * DPAD + m];
#pragma unroll
                for (int jj = 0; jj < 16; jj++) rk[jj] += (km < kj[jj]) ? 1 : 0;
            }
#pragma unroll
            for (int jj = 0; jj < 16; jj++)
                if (rk[jj] < KNN) idxs[i * KNN + rk[jj]] = jb + jj;
        }
        __syncthreads();  // keys dead; GEMM may overwrite As
        gemm_raw(Xs, g_Wcp, As, t);         // 'a' = X @ (Wt - Wb)
        gemm_raw(Xs, g_Wcp + 128, Ps, t);   // 'p' = X @ Wb
        __syncthreads();
        // gather-max: warp-per-node. 32 lanes read a FULL contiguous row per neighbor
        // (512B LDS.128, conflict-free). 2 nodes in flight per iteration for ILP.
        {
            int w = t >> 5, lane = t & 31;
#pragma unroll
            for (int p = 0; p < 4; p++) {
                int n0 = w * 8 + 2 * p;
                int n1 = n0 + 1;
                float4 m0 = make_float4(-3.4e38f, -3.4e38f, -3.4e38f, -3.4e38f);
                float4 m1 = m0;
#pragma unroll 6
                for (int k = 0; k < KNN; k++) {
                    int i0 = idxs[n0 * KNN + k];   // broadcast
                    int i1 = idxs[n1 * KNN + k];   // broadcast
                    float4 v0 = *(const float4*)(Ps + i0 * NPAD + lane * 4);
                    float4 v1 = *(const float4*)(Ps + i1 * NPAD + lane * 4);
                    m0.x = fmaxf(m0.x, v0.x); m0.y = fmaxf(m0.y, v0.y);
                    m0.z = fmaxf(m0.z, v0.z); m0.w = fmaxf(m0.w, v0.w);
                    m1.x = fmaxf(m1.x, v1.x); m1.y = fmaxf(m1.y, v1.y);
                    m1.z = fmaxf(m1.z, v1.z); m1.w = fmaxf(m1.w, v1.w);
                }
                float4 a0 = *(const float4*)(As + n0 * NPAD + lane * 4);
                float4 a1 = *(const float4*)(As + n1 * NPAD + lane * 4);
                float4 bcv = *(const float4*)(bc + lane * 4);
                float4 r0, r1;
                r0.x = elu1(m0.x + a0.x + bcv.x);
                r0.y = elu1(m0.y + a0.y + bcv.y);
                r0.z = elu1(m0.z + a0.z + bcv.z);
                r0.w = elu1(m0.w + a0.w + bcv.w);
                r1.x = elu1(m1.x + a1.x + bcv.x);
                r1.y = elu1(m1.y + a1.y + bcv.y);
                r1.z = elu1(m1.z + a1.z + bcv.z);
                r1.w = elu1(m1.w + a1.w + bcv.w);
                *(float4*)(Xs + n0 * NPAD + lane * 4) = r0;
                *(float4*)(Xs + n1 * NPAD + lane * 4) = r1;
            }
        }
    }
    __syncthreads();

    // ---------------- pool + head MLP ----------------
    float* pooled = hd;        // 128
    float* o1 = hd + 128;      // 64
    float* o2 = hd + 192;      // 32
    float* o3 = hd + 224;      // 32
    if (t < 128) {
        float s = 0.f;
#pragma unroll 8
        for (int n = 0; n < NN; n++) s += Xs[n * NPAD + t];
        pooled[t] = s;
    }
    __syncthreads();
    if (t < 64) {
        float s = bo1[t];
        for (int k = 0; k < 128; k++) s = fmaf(pooled[k], Wo1[k * 64 + t], s);
        o1[t] = elu1(s);
    }
    __syncthreads();
    if (t < 32) {
        float s = bo2[t];
        for (int k = 0; k < 64; k++) s = fmaf(o1[k], Wo2[k * 32 + t], s);
        o2[t] = elu1(s);
    }
    __syncthreads();
    if (t < 32) {
        float s = bo3[t];
        for (int k = 0; k < 32; k++) s = fmaf(o2[k], Wo3[k * 32 + t], s);
        o3[t] = elu1(s);
    }
    __syncthreads();
    if (t < 8) {
        float s = bo4[t];
        for (int k = 0; k < 32; k++) s = fmaf(o3[k], Wo4[k * 8 + t], s);
        out[g * 8 + t] = s;
    }
    if (write_batch) {
        for (int l = t; l < NN; l += NT)
            out[NG * 8 + g * NN + l] = (float)g;
    }
}

static const int SMEM_BYTES = (NN * NPAD * 3 + NN * KNN + NN + 256) * 4;  // 108800

extern "C" void kernel_launch(void* const* d_in, const int* in_sizes, int n_in,
                              void* d_out, int out_size) {
    const float* x_pf = (const float*)d_in[0];
    // d_in[1] = batch_pf (implicit: node n belongs to graph n/64)
    const float* W1  = (const float*)d_in[2];
    const float* b1  = (const float*)d_in[3];
    const float* W2  = (const float*)d_in[4];
    const float* b2  = (const float*)d_in[5];
    const float* Wc  = (const float*)d_in[6];
    const float* bc  = (const float*)d_in[7];
    const float* Wo1 = (const float*)d_in[8];
    const float* bo1 = (const float*)d_in[9];
    const float* Wo2 = (const float*)d_in[10];
    const float* bo2 = (const float*)d_in[11];
    const float* Wo3 = (const float*)d_in[12];
    const float* bo3 = (const float*)d_in[13];
    const float* Wo4 = (const float*)d_in[14];
    const float* bo4 = (const float*)d_in[15];

    cudaFuncSetAttribute(net_kernel, cudaFuncAttributeMaxDynamicSharedMemorySize, SMEM_BYTES);

    prep_kernel<<<100, 256>>>(Wc, W1, W2);

    int write_batch = (out_size >= NG * 8 + NG * NN) ? 1 : 0;
    net_kernel<<<NG, NT, SMEM_BYTES>>>(x_pf, b1, b2, bc,
                                       Wo1, bo1, Wo2, bo2, Wo3, bo3, Wo4, bo4,
                                       (float*)d_out, write_batch);
}

// round 7
// speedup vs baseline: 4.3847x; 1.5263x over previous
#include <cuda_runtime.h>
#include <cuda_bf16.h>

typedef unsigned long long u64;

#define NG   256
#define NN   64
#define KNN  24
#define HID  128
#define NPAD 132   // float stride for fp32 64x128 tiles
#define DPAD 68    // uint stride for 64x64 key matrix
#define XPS  66    // u32 stride for packed bf16 planes
#define NT   256   // threads per CTA

// fragment-ordered bf16 edge weights: [part 2][split 2][kstep 8][ntile 16][lane 32][2] u32
__device__ __align__(16) unsigned g_Wfe[2 * 2 * 8 * 16 * 32 * 2];
// k-pair-packed fp32 weights for stage 1
__device__ u64 g_W2p[64 * 128];
__device__ u64 g_W1p[8 * 128];    // K=15 zero-padded to 16

__device__ __forceinline__ void fma2(u64& d, u64 a, u64 b) {
    asm("fma.rn.f32x2 %0, %1, %2, %0;" : "+l"(d) : "l"(a), "l"(b));
}
__device__ __forceinline__ float2 upk(u64 v) {
    float2 f; asm("mov.b64 {%0, %1}, %2;" : "=f"(f.x), "=f"(f.y) : "l"(v)); return f;
}
__device__ __forceinline__ u64 pk(float lo, float hi) {
    u64 r; asm("mov.b64 %0, {%1, %2};" : "=l"(r) : "f"(lo), "f"(hi)); return r;
}
__device__ __forceinline__ float hadd(u64 v) {
    float2 f = upk(v); return f.x + f.y;
}
__device__ __forceinline__ float elu1(float x) {
    return x > 0.f ? x : (__expf(x) - 1.f);
}
__device__ __forceinline__ unsigned fkey(float d) {
    unsigned u = __float_as_uint(d);
    return ((int)u < 0) ? ~u : (u | 0x80000000u);
}
__device__ __forceinline__ unsigned pkbf2(float a, float b) {
    __nv_bfloat162 h = __floats2bfloat162_rn(a, b);
    return *reinterpret_cast<unsigned*>(&h);
}
__device__ __forceinline__ float bf16f(float v) {
    return __bfloat162float(__float2bfloat16_rn(v));
}

__device__ __forceinline__ void mma_bf16(float* c, const unsigned* a, unsigned b0, unsigned b1) {
    asm volatile("mma.sync.aligned.m16n8k16.row.col.f32.bf16.bf16.f32 "
        "{%0,%1,%2,%3}, {%4,%5,%6,%7}, {%8,%9}, {%0,%1,%2,%3};\n"
        : "+f"(c[0]), "+f"(c[1]), "+f"(c[2]), "+f"(c[3])
        : "r"(a[0]), "r"(a[1]), "r"(a[2]), "r"(a[3]), "r"(b0), "r"(b1));
}

// Wcat(k, cc): cc<128 -> Wc_top - Wc_bot ('a' weights); else Wc_bot ('p' weights)
__device__ __forceinline__ float wcat(const float* Wc, int k, int cc) {
    if (cc < HID) return Wc[k * HID + cc] - Wc[(HID + k) * HID + cc];
    return Wc[(HID + k) * HID + (cc - HID)];
}

__global__ void prep_kernel(const float* __restrict__ Wc,
                            const float* __restrict__ W1,
                            const float* __restrict__ W2) {
    int i = blockIdx.x * blockDim.x + threadIdx.x;
    if (i < 32768) {
        // decompose flat index: [part][sp][ks][nt][lane][r]
        int r = i & 1, L = (i >> 1) & 31, nt = (i >> 6) & 15;
        int ks = (i >> 10) & 7, sp = (i >> 13) & 1, part = (i >> 14) & 1;
        int c  = nt * 8 + (L >> 2);
        int k0 = ks * 16 + (L & 3) * 2 + r * 8;
        int cc = part * HID + c;
        float v0 = wcat(Wc, k0, cc);
        float v1 = wcat(Wc, k0 + 1, cc);
        unsigned u;
        if (sp == 0) u = pkbf2(v0, v1);
        else         u = pkbf2(v0 - bf16f(v0), v1 - bf16f(v1));
        g_Wfe[i] = u;
    }
    int j = i - 32768;
    if (j >= 0 && j < 64 * 128) {
        int kp = j >> 7, c = j & 127;
        g_W2p[j] = pk(W2[(2 * kp) * HID + c], W2[(2 * kp + 1) * HID + c]);
    }
    int l = i - 32768 - 64 * 128;
    if (l >= 0 && l < 8 * 128) {
        int kp = l >> 7, c = l & 127;
        float lo = W1[(2 * kp) * HID + c];
        float hi = (2 * kp + 1 < 15) ? W1[(2 * kp + 1) * HID + c] : 0.f;
        g_W1p[l] = pk(lo, hi);
    }
}

// Out[64x128] = elu( Xin[64 x 2*KP] @ W + bias ). 256 threads, 8 rows x 4 cols per thread.
__device__ __forceinline__ void gemm_act(const float* __restrict__ Xin, int xs, int KP,
                                         const u64* __restrict__ Wp,
                                         const float* __restrict__ bias,
                                         float* __restrict__ Out, int t) {
    int n0 = (t >> 5) * 8;
    int c0 = (t & 31) * 4;
    u64 acc[8][4];
#pragma unroll
    for (int i = 0; i < 8; i++) { acc[i][0] = 0; acc[i][1] = 0; acc[i][2] = 0; acc[i][3] = 0; }
#pragma unroll 4
    for (int kp = 0; kp < KP; kp++) {
        const u64* wr = Wp + kp * 128 + c0;
        ulonglong2 wa = *(const ulonglong2*)(wr);
        ulonglong2 wb = *(const ulonglong2*)(wr + 2);
        u64 xv[8];
#pragma unroll
        for (int i = 0; i < 8; i++) xv[i] = *(const u64*)(Xin + (n0 + i) * xs + 2 * kp);
#pragma unroll
        for (int i = 0; i < 8; i++) {
            fma2(acc[i][0], xv[i], wa.x);
            fma2(acc[i][1], xv[i], wa.y);
            fma2(acc[i][2], xv[i], wb.x);
            fma2(acc[i][3], xv[i], wb.y);
        }
    }
    float4 b = *(const float4*)(bias + c0);
#pragma unroll
    for (int i = 0; i < 8; i++) {
        float4 r;
        r.x = elu1(hadd(acc[i][0]) + b.x);
        r.y = elu1(hadd(acc[i][1]) + b.y);
        r.z = elu1(hadd(acc[i][2]) + b.z);
        r.w = elu1(hadd(acc[i][3]) + b.w);
        *(float4*)(Out + (n0 + i) * NPAD + c0) = r;
    }
}

// Edge gemm on tensor cores with bf16 hi/lo split.
// Xp: packed bf16 hi plane [64][XPS] u32, lo plane at +64*XPS (lives in Ap region).
// Warps 0-3: 'a' output (rows 16w..); warps 4-7: 'p' output.
// Internal barrier before epilogue so writes may overwrite Xp / keys.
__device__ void gemm_edge_mma(const unsigned* __restrict__ Xp,
                              float* __restrict__ Aout,
                              float* __restrict__ Pout, int t) {
    int w = t >> 5, L = t & 31;
    int part = w >> 2;
    int m0 = (w & 3) * 16;
    const unsigned* xh = Xp + (m0 + (L >> 2)) * XPS + (L & 3);
    const unsigned* xl = xh + 64 * XPS;
    float acc[16][4];
#pragma unroll
    for (int nt = 0; nt < 16; nt++) {
        acc[nt][0] = 0.f; acc[nt][1] = 0.f; acc[nt][2] = 0.f; acc[nt][3] = 0.f;
    }
    const unsigned* wb = g_Wfe + part * 16384 + L * 2;
#pragma unroll
    for (int ks = 0; ks < 8; ks++) {
        unsigned ah[4], al[4];
        ah[0] = xh[ks * 8];         ah[1] = xh[8 * XPS + ks * 8];
        ah[2] = xh[ks * 8 + 4];     ah[3] = xh[8 * XPS + ks * 8 + 4];
        al[0] = xl[ks * 8];         al[1] = xl[8 * XPS + ks * 8];
        al[2] = xl[ks * 8 + 4];     al[3] = xl[8 * XPS + ks * 8 + 4];
#pragma unroll
        for (int nt = 0; nt < 16; nt++) {
            const unsigned* wp = wb + (ks * 16 + nt) * 64;
            uint2 bh = *(const uint2*)(wp);
            uint2 bl = *(const uint2*)(wp + 8192);
            mma_bf16(acc[nt], ah, bh.x, bh.y);   // hi*hi
            mma_bf16(acc[nt], ah, bl.x, bl.y);   // hi*lo
            mma_bf16(acc[nt], al, bh.x, bh.y);   // lo*hi
        }
    }
    __syncthreads();   // all Xp/key reads done; safe to overwrite Ap and Ps
    float* dst = part ? Pout : Aout;
    int row = m0 + (L >> 2);
    int col0 = (L & 3) * 2;
#pragma unroll
    for (int nt = 0; nt < 16; nt++) {
        *(float2*)(dst + row * NPAD + nt * 8 + col0)       = make_float2(acc[nt][0], acc[nt][1]);
        *(float2*)(dst + (row + 8) * NPAD + nt * 8 + col0) = make_float2(acc[nt][2], acc[nt][3]);
    }
}

// smem layout (floats)
#define OFF_XS  0
#define OFF_AP  (NN * NPAD)            // 8448: As fp32 / bf16 Xp planes / Xi scratch
#define OFF_PS  (2 * NN * NPAD)        // 16896: Ps fp32 / distance keys / h1 scratch
#define OFF_IDX (3 * NN * NPAD)        // 25344
#define OFF_SQ  (OFF_IDX + NN * KNN / 1 + 0)   // after 1536 ints
#define SMEM_FLOATS (OFF_IDX + NN * KNN + NN + 256)

__global__ __launch_bounds__(NT, 2)
void net_kernel(const float* __restrict__ x_pf,
                const float* __restrict__ b1, const float* __restrict__ b2,
                const float* __restrict__ bc,
                const float* __restrict__ Wo1, const float* __restrict__ bo1,
                const float* __restrict__ Wo2, const float* __restrict__ bo2,
                const float* __restrict__ Wo3, const float* __restrict__ bo3,
                const float* __restrict__ Wo4, const float* __restrict__ bo4,
                float* __restrict__ out, int write_batch) {
    extern __shared__ __align__(16) float sm[];
    float* Xs = sm + OFF_XS;
    float* Ap = sm + OFF_AP;
    float* Ps = sm + OFF_PS;
    int*   idxs = (int*)(sm + OFF_IDX);
    float* sq = sm + OFF_IDX + NN * KNN;
    float* hd = sq + NN;
    unsigned* dsu = (unsigned*)Ps;     // distance keys live in Ps window
    unsigned* Xp  = (unsigned*)Ap;     // bf16 planes live in Ap window

    int g = blockIdx.x;
    int t = threadIdx.x;

    // ---------------- Stage 1: h = elu(elu(x@W1+b1)@W2+b2) ----------------
    float* Xi = Ap;  // temp [64][16], col 15 zeroed
    for (int i = t; i < NN * 16; i += NT) {
        int n = i >> 4, f = i & 15;
        Xi[i] = (f < 15) ? x_pf[(g * NN + n) * 15 + f] : 0.f;
    }
    __syncthreads();
    gemm_act(Xi, 16, 8, g_W1p, b1, Ps, t);
    __syncthreads();
    gemm_act(Ps, NPAD, 64, g_W2p, b2, Xs, t);

    // ---------------- 3 x EdgeConv ----------------
    for (int layer = 0; layer < 3; layer++) {
        __syncthreads();  // Xs ready; Ap free (gather done reading As)
        // convert Xs -> packed bf16 hi/lo planes (A fragments), + squared norms
        {
            int n = t >> 2, cb = (t & 3) * 32;
            unsigned* xph = Xp + n * XPS + cb / 2;
            unsigned* xpl = xph + 64 * XPS;
            const float* src = Xs + n * NPAD + cb;
#pragma unroll
            for (int i = 0; i < 8; i++) {
                float4 v = *(const float4*)(src + i * 4);
                __nv_bfloat162 h01 = __floats2bfloat162_rn(v.x, v.y);
                __nv_bfloat162 h23 = __floats2bfloat162_rn(v.z, v.w);
                float2 hf01 = __bfloat1622float2(h01);
                float2 hf23 = __bfloat1622float2(h23);
                __nv_bfloat162 l01 = __floats2bfloat162_rn(v.x - hf01.x, v.y - hf01.y);
                __nv_bfloat162 l23 = __floats2bfloat162_rn(v.z - hf23.x, v.w - hf23.y);
                xph[i * 2]     = *reinterpret_cast<unsigned*>(&h01);
                xph[i * 2 + 1] = *reinterpret_cast<unsigned*>(&h23);
                xpl[i * 2]     = *reinterpret_cast<unsigned*>(&l01);
                xpl[i * 2 + 1] = *reinterpret_cast<unsigned*>(&l23);
            }
        }
        if (t < NN) {
            u64 a0 = 0, a1 = 0;
#pragma unroll 8
            for (int k4 = 0; k4 < 32; k4++) {
                ulonglong2 v = *(const ulonglong2*)(Xs + t * NPAD + k4 * 4);
                fma2(a0, v.x, v.x);
                fma2(a1, v.y, v.y);
            }
            sq[t] = hadd(a0) + hadd(a1);
        }
        __syncthreads();
        // pairwise distance keys (exact fp32), written into Ps window
        {
            int r0 = (t >> 4) * 4;
            int cbase = t & 15;
            u64 acc2[4][4];
#pragma unroll
            for (int i = 0; i < 4; i++)
#pragma unroll
                for (int j = 0; j < 4; j++) acc2[i][j] = 0;
#pragma unroll 2
            for (int k4 = 0; k4 < 32; k4++) {
                ulonglong2 av[4], bv[4];
#pragma unroll
                for (int i = 0; i < 4; i++) av[i] = *(const ulonglong2*)(Xs + (r0 + i) * NPAD + k4 * 4);
#pragma unroll
                for (int j = 0; j < 4; j++) bv[j] = *(const ulonglong2*)(Xs + (cbase + 16 * j) * NPAD + k4 * 4);
#pragma unroll
                for (int i = 0; i < 4; i++)
#pragma unroll
                    for (int j = 0; j < 4; j++) {
                        fma2(acc2[i][j], av[i].x, bv[j].x);
                        fma2(acc2[i][j], av[i].y, bv[j].y);
                    }
            }
#pragma unroll
            for (int i = 0; i < 4; i++)
#pragma unroll
                for (int j = 0; j < 4; j++) {
                    int cc = cbase + 16 * j;
                    float d = sq[r0 + i] + sq[cc] - 2.f * hadd(acc2[i][j]);
                    dsu[(r0 + i) * DPAD + cc] = fkey(d);
                }
        }
        __syncthreads();
        // exact top-K by rank counting
        {
            int i = t >> 2, jb = (t & 3) * 16;
            unsigned kj[16];
#pragma unroll
            for (int jj = 0; jj < 16; jj++) kj[jj] = dsu[i * DPAD + jb + jj];
            int rk[16];
#pragma unroll
            for (int jj = 0; jj < 16; jj++) rk[jj] = 0;
#pragma unroll 4
            for (int m = 0; m < 64; m++) {
                unsigned km = dsu[i * DPAD + m];
#pragma unroll
                for (int jj = 0; jj < 16; jj++) rk[jj] += (km < kj[jj]) ? 1 : 0;
            }
#pragma unroll
            for (int jj = 0; jj < 16; jj++)
                if (rk[jj] < KNN) idxs[i * KNN + rk[jj]] = jb + jj;
        }
        __syncthreads();
        // tensor-core edge gemm (internal barrier, then writes Ap='a', Ps='p')
        gemm_edge_mma(Xp, Ap, Ps, t);
        __syncthreads();
        // gather-max: warp-per-node, full contiguous rows, conflict-free
        {
            int w = t >> 5, lane = t & 31;
#pragma unroll
            for (int p = 0; p < 4; p++) {
                int n0 = w * 8 + 2 * p;
                int n1 = n0 + 1;
                float4 m0 = make_float4(-3.4e38f, -3.4e38f, -3.4e38f, -3.4e38f);
                float4 m1 = m0;
#pragma unroll 6
                for (int k = 0; k < KNN; k++) {
                    int i0 = idxs[n0 * KNN + k];
                    int i1 = idxs[n1 * KNN + k];
                    float4 v0 = *(const float4*)(Ps + i0 * NPAD + lane * 4);
                    float4 v1 = *(const float4*)(Ps + i1 * NPAD + lane * 4);
                    m0.x = fmaxf(m0.x, v0.x); m0.y = fmaxf(m0.y, v0.y);
                    m0.z = fmaxf(m0.z, v0.z); m0.w = fmaxf(m0.w, v0.w);
                    m1.x = fmaxf(m1.x, v1.x); m1.y = fmaxf(m1.y, v1.y);
                    m1.z = fmaxf(m1.z, v1.z); m1.w = fmaxf(m1.w, v1.w);
                }
                float4 a0 = *(const float4*)(Ap + n0 * NPAD + lane * 4);
                float4 a1 = *(const float4*)(Ap + n1 * NPAD + lane * 4);
                float4 bcv = *(const float4*)(bc + lane * 4);
                float4 r0, r1;
                r0.x = elu1(m0.x + a0.x + bcv.x);
                r0.y = elu1(m0.y + a0.y + bcv.y);
                r0.z = elu1(m0.z + a0.z + bcv.z);
                r0.w = elu1(m0.w + a0.w + bcv.w);
                r1.x = elu1(m1.x + a1.x + bcv.x);
                r1.y = elu1(m1.y + a1.y + bcv.y);
                r1.z = elu1(m1.z + a1.z + bcv.z);
                r1.w = elu1(m1.w + a1.w + bcv.w);
                *(float4*)(Xs + n0 * NPAD + lane * 4) = r0;
                *(float4*)(Xs + n1 * NPAD + lane * 4) = r1;
            }
        }
    }
    __syncthreads();

    // ---------------- pool + head MLP ----------------
    float* pooled = hd;        // 128
    float* o1 = hd + 128;      // 64
    float* o2 = hd + 192;      // 32
    float* o3 = hd + 224;      // 32
    if (t < 128) {
        float s = 0.f;
#pragma unroll 8
        for (int n = 0; n < NN; n++) s += Xs[n * NPAD + t];
        pooled[t] = s;
    }
    __syncthreads();
    if (t < 64) {
        float s = bo1[t];
        for (int k = 0; k < 128; k++) s = fmaf(pooled[k], Wo1[k * 64 + t], s);
        o1[t] = elu1(s);
    }
    __syncthreads();
    if (t < 32) {
        float s = bo2[t];
        for (int k = 0; k < 64; k++) s = fmaf(o1[k], Wo2[k * 32 + t], s);
        o2[t] = elu1(s);
    }
    __syncthreads();
    if (t < 32) {
        float s = bo3[t];
        for (int k = 0; k < 32; k++) s = fmaf(o2[k], Wo3[k * 32 + t], s);
        o3[t] = elu1(s);
    }
    __syncthreads();
    if (t < 8) {
        float s = bo4[t];
        for (int k = 0; k < 32; k++) s = fmaf(o3[k], Wo4[k * 8 + t], s);
        out[g * 8 + t] = s;
    }
    if (write_batch) {
        for (int l = t; l < NN; l += NT)
            out[NG * 8 + g * NN + l] = (float)g;
    }
}

static const int SMEM_BYTES = SMEM_FLOATS * 4;  // 108800

extern "C" void kernel_launch(void* const* d_in, const int* in_sizes, int n_in,
                              void* d_out, int out_size) {
    const float* x_pf = (const float*)d_in[0];
    // d_in[1] = batch_pf (implicit: node n belongs to graph n/64)
    const float* W1  = (const float*)d_in[2];
    const float* b1  = (const float*)d_in[3];
    const float* W2  = (const float*)d_in[4];
    const float* b2  = (const float*)d_in[5];
    const float* Wc  = (const float*)d_in[6];
    const float* bc  = (const float*)d_in[7];
    const float* Wo1 = (const float*)d_in[8];
    const float* bo1 = (const float*)d_in[9];
    const float* Wo2 = (const float*)d_in[10];
    const float* bo2 = (const float*)d_in[11];
    const float* Wo3 = (const float*)d_in[12];
    const float* bo3 = (const float*)d_in[13];
    const float* Wo4 = (const float*)d_in[14];
    const float* bo4 = (const float*)d_in[15];

    cudaFuncSetAttribute(net_kernel, cudaFuncAttributeMaxDynamicSharedMemorySize, SMEM_BYTES);

    prep_kernel<<<164, 256>>>(Wc, W1, W2);

    int write_batch = (out_size >= NG * 8 + NG * NN) ? 1 : 0;
    net_kernel<<<NG, NT, SMEM_BYTES>>>(x_pf, b1, b2, bc,
                                       Wo1, bo1, Wo2, bo2, Wo3, bo3, Wo4, bo4,
                                       (float*)d_out, write_batch);
}

// round 9
// speedup vs baseline: 4.6681x; 1.0646x over previous
#include <cuda_runtime.h>
#include <cuda_bf16.h>

typedef unsigned long long u64;

#define NG   256
#define NN   64
#define KNN  24
#define HID  128
#define NPAD 132   // float stride for fp32 64x128 tiles
#define DPAD 68    // uint stride for 64x64 key matrix
#define XPS  66    // u32 stride for packed bf16 planes
#define NT   256   // threads per CTA

// fragment-ordered bf16 edge weights: [part 2][split 2][kstep 8][ntile 16][lane 32][2] u32
__device__ __align__(16) unsigned g_Wfe[2 * 2 * 8 * 16 * 32 * 2];
// k-pair-packed fp32 weights for stage 1
__device__ u64 g_W2p[64 * 128];
__device__ u64 g_W1p[8 * 128];    // K=15 zero-padded to 16

__device__ __forceinline__ void fma2(u64& d, u64 a, u64 b) {
    asm("fma.rn.f32x2 %0, %1, %2, %0;" : "+l"(d) : "l"(a), "l"(b));
}
__device__ __forceinline__ float2 upk(u64 v) {
    float2 f; asm("mov.b64 {%0, %1}, %2;" : "=f"(f.x), "=f"(f.y) : "l"(v)); return f;
}
__device__ __forceinline__ u64 pk(float lo, float hi) {
    u64 r; asm("mov.b64 %0, {%1, %2};" : "=l"(r) : "f"(lo), "f"(hi)); return r;
}
__device__ __forceinline__ float hadd(u64 v) {
    float2 f = upk(v); return f.x + f.y;
}
__device__ __forceinline__ float elu1(float x) {
    return x > 0.f ? x : (__expf(x) - 1.f);
}
__device__ __forceinline__ unsigned fkey(float d) {
    unsigned u = __float_as_uint(d);
    return ((int)u < 0) ? ~u : (u | 0x80000000u);
}
__device__ __forceinline__ unsigned pkbf2(float a, float b) {
    __nv_bfloat162 h = __floats2bfloat162_rn(a, b);
    return *reinterpret_cast<unsigned*>(&h);
}
__device__ __forceinline__ float bf16f(float v) {
    return __bfloat162float(__float2bfloat16_rn(v));
}

__device__ __forceinline__ void mma_bf16(float* c, const unsigned* a, unsigned b0, unsigned b1) {
    asm volatile("mma.sync.aligned.m16n8k16.row.col.f32.bf16.bf16.f32 "
        "{%0,%1,%2,%3}, {%4,%5,%6,%7}, {%8,%9}, {%0,%1,%2,%3};\n"
        : "+f"(c[0]), "+f"(c[1]), "+f"(c[2]), "+f"(c[3])
        : "r"(a[0]), "r"(a[1]), "r"(a[2]), "r"(a[3]), "r"(b0), "r"(b1));
}

// Wcat(k, cc): cc<128 -> Wc_top - Wc_bot ('a' weights); else Wc_bot ('p' weights)
__device__ __forceinline__ float wcat(const float* Wc, int k, int cc) {
    if (cc < HID) return Wc[k * HID + cc] - Wc[(HID + k) * HID + cc];
    return Wc[(HID + k) * HID + (cc - HID)];
}

__global__ void prep_kernel(const float* __restrict__ Wc,
                            const float* __restrict__ W1,
                            const float* __restrict__ W2) {
    int i = blockIdx.x * blockDim.x + threadIdx.x;
    if (i < 32768) {
        int r = i & 1, L = (i >> 1) & 31, nt = (i >> 6) & 15;
        int ks = (i >> 10) & 7, sp = (i >> 13) & 1, part = (i >> 14) & 1;
        int c  = nt * 8 + (L >> 2);
        int k0 = ks * 16 + (L & 3) * 2 + r * 8;
        int cc = part * HID + c;
        float v0 = wcat(Wc, k0, cc);
        float v1 = wcat(Wc, k0 + 1, cc);
        unsigned u;
        if (sp == 0) u = pkbf2(v0, v1);
        else         u = pkbf2(v0 - bf16f(v0), v1 - bf16f(v1));
        g_Wfe[i] = u;
    }
    int j = i - 32768;
    if (j >= 0 && j < 64 * 128) {
        int kp = j >> 7, c = j & 127;
        g_W2p[j] = pk(W2[(2 * kp) * HID + c], W2[(2 * kp + 1) * HID + c]);
    }
    int l = i - 32768 - 64 * 128;
    if (l >= 0 && l < 8 * 128) {
        int kp = l >> 7, c = l & 127;
        float lo = W1[(2 * kp) * HID + c];
        float hi = (2 * kp + 1 < 15) ? W1[(2 * kp + 1) * HID + c] : 0.f;
        g_W1p[l] = pk(lo, hi);
    }
}

// Out[64x128] = elu( Xin[64 x 2*KP] @ W + bias ). 256 threads, 8 rows x 4 cols per thread.
__device__ __forceinline__ void gemm_act(const float* __restrict__ Xin, int xs, int KP,
                                         const u64* __restrict__ Wp,
                                         const float* __restrict__ bias,
                                         float* __restrict__ Out, int t) {
    int n0 = (t >> 5) * 8;
    int c0 = (t & 31) * 4;
    u64 acc[8][4];
#pragma unroll
    for (int i = 0; i < 8; i++) { acc[i][0] = 0; acc[i][1] = 0; acc[i][2] = 0; acc[i][3] = 0; }
#pragma unroll 4
    for (int kp = 0; kp < KP; kp++) {
        const u64* wr = Wp + kp * 128 + c0;
        ulonglong2 wa = *(const ulonglong2*)(wr);
        ulonglong2 wb = *(const ulonglong2*)(wr + 2);
        u64 xv[8];
#pragma unroll
        for (int i = 0; i < 8; i++) xv[i] = *(const u64*)(Xin + (n0 + i) * xs + 2 * kp);
#pragma unroll
        for (int i = 0; i < 8; i++) {
            fma2(acc[i][0], xv[i], wa.x);
            fma2(acc[i][1], xv[i], wa.y);
            fma2(acc[i][2], xv[i], wb.x);
            fma2(acc[i][3], xv[i], wb.y);
        }
    }
    float4 b = *(const float4*)(bias + c0);
#pragma unroll
    for (int i = 0; i < 8; i++) {
        float4 r;
        r.x = elu1(hadd(acc[i][0]) + b.x);
        r.y = elu1(hadd(acc[i][1]) + b.y);
        r.z = elu1(hadd(acc[i][2]) + b.z);
        r.w = elu1(hadd(acc[i][3]) + b.w);
        *(float4*)(Out + (n0 + i) * NPAD + c0) = r;
    }
}

// Edge gemm on tensor cores with bf16 hi/lo split (3 terms).
__device__ void gemm_edge_mma(const unsigned* __restrict__ Xp,
                              float* __restrict__ Aout,
                              float* __restrict__ Pout, int t) {
    int w = t >> 5, L = t & 31;
    int part = w >> 2;
    int m0 = (w & 3) * 16;
    const unsigned* xh = Xp + (m0 + (L >> 2)) * XPS + (L & 3);
    const unsigned* xl = xh + 64 * XPS;
    float acc[16][4];
#pragma unroll
    for (int nt = 0; nt < 16; nt++) {
        acc[nt][0] = 0.f; acc[nt][1] = 0.f; acc[nt][2] = 0.f; acc[nt][3] = 0.f;
    }
    const unsigned* wb = g_Wfe + part * 16384 + L * 2;
#pragma unroll
    for (int ks = 0; ks < 8; ks++) {
        unsigned ah[4], al[4];
        ah[0] = xh[ks * 8];         ah[1] = xh[8 * XPS + ks * 8];
        ah[2] = xh[ks * 8 + 4];     ah[3] = xh[8 * XPS + ks * 8 + 4];
        al[0] = xl[ks * 8];         al[1] = xl[8 * XPS + ks * 8];
        al[2] = xl[ks * 8 + 4];     al[3] = xl[8 * XPS + ks * 8 + 4];
#pragma unroll
        for (int nt = 0; nt < 16; nt++) {
            const unsigned* wp = wb + (ks * 16 + nt) * 64;
            uint2 bh = *(const uint2*)(wp);
            uint2 bl = *(const uint2*)(wp + 8192);
            mma_bf16(acc[nt], ah, bh.x, bh.y);   // hi*hi
            mma_bf16(acc[nt], ah, bl.x, bl.y);   // hi*lo
            mma_bf16(acc[nt], al, bh.x, bh.y);   // lo*hi
        }
    }
    __syncthreads();   // all Xp/key reads done; safe to overwrite Ap and Ps
    float* dst = part ? Pout : Aout;
    int row = m0 + (L >> 2);
    int col0 = (L & 3) * 2;
#pragma unroll
    for (int nt = 0; nt < 16; nt++) {
        *(float2*)(dst + row * NPAD + nt * 8 + col0)       = make_float2(acc[nt][0], acc[nt][1]);
        *(float2*)(dst + (row + 8) * NPAD + nt * 8 + col0) = make_float2(acc[nt][2], acc[nt][3]);
    }
}

// Distance Gram on tensor cores, 4-term bf16 split (hh+hl+lh+ll).
// Warp w: rows 16*(w&3).. , cols 32*(w>>2).. (4 ntiles of 8). Writes fkey(d) into dsu.
__device__ void dist_mma(const unsigned* __restrict__ Xp,
                         const float* __restrict__ sq,
                         unsigned* __restrict__ dsu, int t) {
    int w = t >> 5, L = t & 31;
    int m0 = (w & 3) * 16;
    int nbase = (w >> 2) * 32;
    const unsigned* xh = Xp + (m0 + (L >> 2)) * XPS + (L & 3);
    const unsigned* xl = xh + 64 * XPS;
    const unsigned* bbase = Xp + (nbase + (L >> 2)) * XPS + (L & 3);
    float acc[4][4];
#pragma unroll
    for (int nt = 0; nt < 4; nt++) {
        acc[nt][0] = 0.f; acc[nt][1] = 0.f; acc[nt][2] = 0.f; acc[nt][3] = 0.f;
    }
#pragma unroll
    for (int ks = 0; ks < 8; ks++) {
        unsigned ah[4], al[4];
        ah[0] = xh[ks * 8];         ah[1] = xh[8 * XPS + ks * 8];
        ah[2] = xh[ks * 8 + 4];     ah[3] = xh[8 * XPS + ks * 8 + 4];
        al[0] = xl[ks * 8];         al[1] = xl[8 * XPS + ks * 8];
        al[2] = xl[ks * 8 + 4];     al[3] = xl[8 * XPS + ks * 8 + 4];
#pragma unroll
        for (int nt = 0; nt < 4; nt++) {
            const unsigned* bh = bbase + nt * 8 * XPS + ks * 8;
            const unsigned* bl = bh + 64 * XPS;
            unsigned bh0 = bh[0], bh1 = bh[4];
            unsigned bl0 = bl[0], bl1 = bl[4];
            mma_bf16(acc[nt], ah, bh0, bh1);
            mma_bf16(acc[nt], ah, bl0, bl1);
            mma_bf16(acc[nt], al, bh0, bh1);
            mma_bf16(acc[nt], al, bl0, bl1);
        }
    }
    int r0 = m0 + (L >> 2);
    float si0 = sq[r0], si1 = sq[r0 + 8];
#pragma unroll
    for (int nt = 0; nt < 4; nt++) {
        int c0 = nbase + nt * 8 + (L & 3) * 2;
        float sj0 = sq[c0], sj1 = sq[c0 + 1];
        dsu[r0 * DPAD + c0]           = fkey(si0 + sj0 - 2.f * acc[nt][0]);
        dsu[r0 * DPAD + c0 + 1]       = fkey(si0 + sj1 - 2.f * acc[nt][1]);
        dsu[(r0 + 8) * DPAD + c0]     = fkey(si1 + sj0 - 2.f * acc[nt][2]);
        dsu[(r0 + 8) * DPAD + c0 + 1] = fkey(si1 + sj1 - 2.f * acc[nt][3]);
    }
}

// smem layout (floats)
#define OFF_XS  0
#define OFF_AP  (NN * NPAD)            // 8448: As fp32 / bf16 Xp planes / Xi scratch
#define OFF_PS  (2 * NN * NPAD)        // 16896: Ps fp32 / distance keys / h1 scratch
#define OFF_IDX (3 * NN * NPAD)        // 25344
#define SMEM_FLOATS (OFF_IDX + NN * KNN + NN + 256)

__global__ __launch_bounds__(NT, 2)
void net_kernel(const float* __restrict__ x_pf,
                const float* __restrict__ b1, const float* __restrict__ b2,
                const float* __restrict__ bc,
                const float* __restrict__ Wo1, const float* __restrict__ bo1,
                const float* __restrict__ Wo2, const float* __restrict__ bo2,
                const float* __restrict__ Wo3, const float* __restrict__ bo3,
                const float* __restrict__ Wo4, const float* __restrict__ bo4,
                float* __restrict__ out, int write_batch) {
    extern __shared__ __align__(16) float sm[];
    float* Xs = sm + OFF_XS;
    float* Ap = sm + OFF_AP;
    float* Ps = sm + OFF_PS;
    int*   idxs = (int*)(sm + OFF_IDX);
    float* sq = sm + OFF_IDX + NN * KNN;
    float* hd = sq + NN;
    unsigned* dsu = (unsigned*)Ps;     // distance keys live in Ps window
    unsigned* Xp  = (unsigned*)Ap;     // bf16 planes live in Ap window

    int g = blockIdx.x;
    int t = threadIdx.x;

    // ---------------- Stage 1: h = elu(elu(x@W1+b1)@W2+b2) ----------------
    float* Xi = Ap;  // temp [64][16], col 15 zeroed
    for (int i = t; i < NN * 16; i += NT) {
        int n = i >> 4, f = i & 15;
        Xi[i] = (f < 15) ? x_pf[(g * NN + n) * 15 + f] : 0.f;
    }
    __syncthreads();
    gemm_act(Xi, 16, 8, g_W1p, b1, Ps, t);
    __syncthreads();
    gemm_act(Ps, NPAD, 64, g_W2p, b2, Xs, t);

    // ---------------- 3 x EdgeConv ----------------
    for (int layer = 0; layer < 3; layer++) {
        __syncthreads();  // Xs ready; Ap free
        // convert Xs -> packed bf16 hi/lo planes + squared norms (exact fp32)
        {
            int n = t >> 2, cb = (t & 3) * 32;
            unsigned* xph = Xp + n * XPS + cb / 2;
            unsigned* xpl = xph + 64 * XPS;
            const float* src = Xs + n * NPAD + cb;
#pragma unroll
            for (int i = 0; i < 8; i++) {
                float4 v = *(const float4*)(src + i * 4);
                __nv_bfloat162 h01 = __floats2bfloat162_rn(v.x, v.y);
                __nv_bfloat162 h23 = __floats2bfloat162_rn(v.z, v.w);
                float2 hf01 = __bfloat1622float2(h01);
                float2 hf23 = __bfloat1622float2(h23);
                __nv_bfloat162 l01 = __floats2bfloat162_rn(v.x - hf01.x, v.y - hf01.y);
                __nv_bfloat162 l23 = __floats2bfloat162_rn(v.z - hf23.x, v.w - hf23.y);
                xph[i * 2]     = *reinterpret_cast<unsigned*>(&h01);
                xph[i * 2 + 1] = *reinterpret_cast<unsigned*>(&h23);
                xpl[i * 2]     = *reinterpret_cast<unsigned*>(&l01);
                xpl[i * 2 + 1] = *reinterpret_cast<unsigned*>(&l23);
            }
        }
        if (t < NN) {
            u64 a0 = 0, a1 = 0;
#pragma unroll 8
            for (int k4 = 0; k4 < 32; k4++) {
                ulonglong2 v = *(const ulonglong2*)(Xs + t * NPAD + k4 * 4);
                fma2(a0, v.x, v.x);
                fma2(a1, v.y, v.y);
            }
            sq[t] = hadd(a0) + hadd(a1);
        }
        __syncthreads();
        // pairwise distance keys via tensor cores (writes dsu in Ps window)
        dist_mma(Xp, sq, dsu, t);
        __syncthreads();
        // exact top-K by rank counting
        {
            int i = t >> 2, jb = (t & 3) * 16;
            unsigned kj[16];
#pragma unroll
            for (int jj = 0; jj < 16; jj++) kj[jj] = dsu[i * DPAD + jb + jj];
            int rk[16];
#pragma unroll
            for (int jj = 0; jj < 16; jj++) rk[jj] = 0;
#pragma unroll 4
            for (int m = 0; m < 64; m++) {
                unsigned km = dsu[i * DPAD + m];
#pragma unroll
                for (int jj = 0; jj < 16; jj++) rk[jj] += (km < kj[jj]) ? 1 : 0;
            }
#pragma unroll
            for (int jj = 0; jj < 16; jj++)
                if (rk[jj] < KNN) idxs[i * KNN + rk[jj]] = jb + jj;
        }
        __syncthreads();
        // tensor-core edge gemm (internal barrier, then writes Ap='a', Ps='p')
        gemm_edge_mma(Xp, Ap, Ps, t);
        __syncthreads();
        // gather-max: warp-per-node, full contiguous rows, conflict-free
        {
            int w = t >> 5, lane = t & 31;
#pragma unroll
            for (int p = 0; p < 4; p++) {
                int n0 = w * 8 + 2 * p;
                int n1 = n0 + 1;
                float4 m0 = make_float4(-3.4e38f, -3.4e38f, -3.4e38f, -3.4e38f);
                float4 m1 = m0;
#pragma unroll 6
                for (int k = 0; k < KNN; k++) {
                    int i0 = idxs[n0 * KNN + k];
                    int i1 = idxs[n1 * KNN + k];
                    float4 v0 = *(const float4*)(Ps + i0 * NPAD + lane * 4);
                    float4 v1 = *(const float4*)(Ps + i1 * NPAD + lane * 4);
                    m0.x = fmaxf(m0.x, v0.x); m0.y = fmaxf(m0.y, v0.y);
                    m0.z = fmaxf(m0.z, v0.z); m0.w = fmaxf(m0.w, v0.w);
                    m1.x = fmaxf(m1.x, v1.x); m1.y = fmaxf(m1.y, v1.y);
                    m1.z = fmaxf(m1.z, v1.z); m1.w = fmaxf(m1.w, v1.w);
                }
                float4 a0 = *(const float4*)(Ap + n0 * NPAD + lane * 4);
                float4 a1 = *(const float4*)(Ap + n1 * NPAD + lane * 4);
                float4 bcv = *(const float4*)(bc + lane * 4);
                float4 r0, r1;
                r0.x = elu1(m0.x + a0.x + bcv.x);
                r0.y = elu1(m0.y + a0.y + bcv.y);
                r0.z = elu1(m0.z + a0.z + bcv.z);
                r0.w = elu1(m0.w + a0.w + bcv.w);
                r1.x = elu1(m1.x + a1.x + bcv.x);
                r1.y = elu1(m1.y + a1.y + bcv.y);
                r1.z = elu1(m1.z + a1.z + bcv.z);
                r1.w = elu1(m1.w + a1.w + bcv.w);
                *(float4*)(Xs + n0 * NPAD + lane * 4) = r0;
                *(float4*)(Xs + n1 * NPAD + lane * 4) = r1;
            }
        }
    }
    __syncthreads();

    // ---------------- pool + head MLP ----------------
    float* pooled = hd;        // 128
    float* o1 = hd + 128;      // 64
    float* o2 = hd + 192;      // 32
    float* o3 = hd + 224;      // 32
    if (t < 128) {
        float s = 0.f;
#pragma unroll 8
        for (int n = 0; n < NN; n++) s += Xs[n * NPAD + t];
        pooled[t] = s;
    }
    __syncthreads();
    if (t < 64) {
        float s = bo1[t];
        for (int k = 0; k < 128; k++) s = fmaf(pooled[k], Wo1[k * 64 + t], s);
        o1[t] = elu1(s);
    }
    __syncthreads();
    if (t < 32) {
        float s = bo2[t];
        for (int k = 0; k < 64; k++) s = fmaf(o1[k], Wo2[k * 32 + t], s);
        o2[t] = elu1(s);
    }
    __syncthreads();
    if (t < 32) {
        float s = bo3[t];
        for (int k = 0; k < 32; k++) s = fmaf(o2[k], Wo3[k * 32 + t], s);
        o3[t] = elu1(s);
    }
    __syncthreads();
    if (t < 8) {
        float s = bo4[t];
        for (int k = 0; k < 32; k++) s = fmaf(o3[k], Wo4[k * 8 + t], s);
        out[g * 8 + t] = s;
    }
    if (write_batch) {
        for (int l = t; l < NN; l += NT)
            out[NG * 8 + g * NN + l] = (float)g;
    }
}

static const int SMEM_BYTES = SMEM_FLOATS * 4;  // 108800

extern "C" void kernel_launch(void* const* d_in, const int* in_sizes, int n_in,
                              void* d_out, int out_size) {
    const float* x_pf = (const float*)d_in[0];
    // d_in[1] = batch_pf (implicit: node n belongs to graph n/64)
    const float* W1  = (const float*)d_in[2];
    const float* b1  = (const float*)d_in[3];
    const float* W2  = (const float*)d_in[4];
    const float* b2  = (const float*)d_in[5];
    const float* Wc  = (const float*)d_in[6];
    const float* bc  = (const float*)d_in[7];
    const float* Wo1 = (const float*)d_in[8];
    const float* bo1 = (const float*)d_in[9];
    const float* Wo2 = (const float*)d_in[10];
    const float* bo2 = (const float*)d_in[11];
    const float* Wo3 = (const float*)d_in[12];
    const float* bo3 = (const float*)d_in[13];
    const float* Wo4 = (const float*)d_in[14];
    const float* bo4 = (const float*)d_in[15];

    cudaFuncSetAttribute(net_kernel, cudaFuncAttributeMaxDynamicSharedMemorySize, SMEM_BYTES);

    prep_kernel<<<164, 256>>>(Wc, W1, W2);

    int write_batch = (out_size >= NG * 8 + NG * NN) ? 1 : 0;
    net_kernel<<<NG, NT, SMEM_BYTES>>>(x_pf, b1, b2, bc,
                                       Wo1, bo1, Wo2, bo2, Wo3, bo3, Wo4, bo4,
                                       (float*)d_out, write_batch);
}